// round 3
// baseline (speedup 1.0000x reference)
#include <cuda_runtime.h>
#include <stdint.h>

#define T_STEPS 15
#define C_IN    6
#define HW      256
#define NPIX    65536
#define C_OUT   64
#define THRESH  15.0f
#define NELEM   62914560         // 15*64*256*256
#define NTAP    150              // 5*5*6, q = (ky*5+kx)*6 + i
#define NCHUNK  10               // 16 tf-bytes per chunk

// device globals (no allocation)
__device__ unsigned char       g_ft[C_IN * NPIX];       // first spike time per (i,pix); 15 = never
__device__ uint4               g_ftq[NCHUNK * NPIX];    // q-ordered tf bytes, [chunk][pix]
__device__ int                 g_winfo[NPIX];           // -1 or wc | (count<<8)
__device__ unsigned char       g_wc[NPIX];              // winner channel (255 = none)
__device__ float               g_firstpot[NPIX];
__device__ float               g_winval[(size_t)NPIX * 16]; // [pix][t] thresholded winner values
__device__ int                 g_vmax = 0;              // float bits of max firstpot (idempotent atomicMax)
__device__ unsigned long long  g_part[64];
__device__ int                 g_banc[5];
__device__ int                 g_banp[5];

// ---------------------------------------------------------------------------
// K0: first-spike time per (input channel, pixel). Spikes are cumulative.
// ---------------------------------------------------------------------------
__global__ __launch_bounds__(256) void ft_kernel(const float* __restrict__ in)
{
    const int idx = blockIdx.x * 256 + threadIdx.x;     // over C_IN*NPIX
    int tf = 15;
#pragma unroll
    for (int t = T_STEPS - 1; t >= 0; t--)
        if (in[(size_t)t * C_IN * NPIX + idx] > 0.f) tf = t;
    g_ft[idx] = (unsigned char)tf;
}

// ---------------------------------------------------------------------------
// K0b: gather tf into per-pixel q-ordered byte stream (16x16 pixel tiles).
// Padding taps (q>=150) get tf=15 (never contribute).
// ---------------------------------------------------------------------------
__global__ __launch_bounds__(256) void ftq_kernel()
{
    __shared__ unsigned char sft[C_IN * 20 * 20];
    const int x0 = blockIdx.x * 16, y0 = blockIdx.y * 16;
    const int tid = threadIdx.x;

    for (int k = tid; k < C_IN * 400; k += 256) {
        const int i = k / 400, rr = k % 400, yy = rr / 20, xx = rr % 20;
        const int gy = y0 + yy - 2, gx = x0 + xx - 2;
        sft[k] = (gy >= 0 && gy < HW && gx >= 0 && gx < HW)
                 ? g_ft[i * NPIX + gy * HW + gx] : (unsigned char)15;
    }
    __syncthreads();

    const int px = tid & 15, py = tid >> 4;
    const int pix = (y0 + py) * HW + x0 + px;

#pragma unroll
    for (int chunk = 0; chunk < NCHUNK; chunk++) {
        unsigned r[4] = {0u, 0u, 0u, 0u};
#pragma unroll
        for (int b = 0; b < 16; b++) {
            const int q = chunk * 16 + b;
            unsigned v = 15u;
            if (q < NTAP) {
                const int ky = q / 30, kx = (q / 6) % 5, i = q % 6;
                v = sft[(i * 20 + py + ky) * 20 + px + kx];
            }
            r[b >> 2] |= v << ((b & 3) * 8);
        }
        g_ftq[chunk * NPIX + pix] = make_uint4(r[0], r[1], r[2], r[3]);
    }
}

// ---------------------------------------------------------------------------
// K1: sparse-exact conv. Warp lanes = 32 channels (tf uniform across warp!),
// 2 warps per pixel slot (ch halves), 4 slots x 16 pixels per 256-thr block.
// Per tap: uniform switch(tf) falls through (15-tf) FADDs -> bitwise identical
// to the dense (ky,kx,i)-ordered fp32 chain (skipping x==0 terms is exact).
// Epilogue resolves te / winner / firstpot per pixel and stores winner values.
// ---------------------------------------------------------------------------
__global__ __launch_bounds__(256) void conv_kernel(const float* __restrict__ wg)
{
    __shared__ float ws[NTAP * 64];               // [q][c], 38400 B
    __shared__ int s_te[8];
    __shared__ unsigned long long s_key[8];

    const int tid = threadIdx.x;
    for (int k = tid; k < 64 * NTAP; k += 256) {  // OIHW -> [q][c]
        const int c = k / NTAP, rr = k % NTAP;
        const int i = rr / 25, r2 = rr % 25, ky = r2 / 5, kx = r2 % 5;
        ws[((ky * 5 + kx) * 6 + i) * 64 + c] = wg[k];
    }
    __syncthreads();

    const int lane = tid & 31;
    const int wid  = tid >> 5;
    const int half = wid & 1;
    const int slot = wid >> 1;
    const int ch   = half * 32 + lane;

    for (int r = 0; r < 16; r++) {
        const int pix = blockIdx.x * 64 + slot * 16 + r;

        float acc[15];
#pragma unroll
        for (int t = 0; t < 15; t++) acc[t] = 0.f;

#pragma unroll
        for (int chunk = 0; chunk < NCHUNK; chunk++) {
            const uint4 T = g_ftq[chunk * NPIX + pix];      // uniform load
            const unsigned Tw[4] = {T.x, T.y, T.z, T.w};
#pragma unroll
            for (int b = 0; b < 16; b++) {
                const int q = chunk * 16 + b;
                if (q < NTAP) {
                    const unsigned tf = (Tw[b >> 2] >> ((b & 3) * 8)) & 0xffu;
                    const float w = ws[q * 64 + ch];
                    switch (tf) {                 // uniform across warp; fallthrough
                        case 0:  acc[0]  += w;
                        case 1:  acc[1]  += w;
                        case 2:  acc[2]  += w;
                        case 3:  acc[3]  += w;
                        case 4:  acc[4]  += w;
                        case 5:  acc[5]  += w;
                        case 6:  acc[6]  += w;
                        case 7:  acc[7]  += w;
                        case 8:  acc[8]  += w;
                        case 9:  acc[9]  += w;
                        case 10: acc[10] += w;
                        case 11: acc[11] += w;
                        case 12: acc[12] += w;
                        case 13: acc[13] += w;
                        case 14: acc[14] += w;
                        default: break;
                    }
                }
            }
        }

        // ---- epilogue: te, winner, firstpot, winner values ----
        int te_l = 15;
#pragma unroll
        for (int t = 14; t >= 0; t--) if (acc[t] >= THRESH) te_l = t;
#pragma unroll
        for (int off = 16; off; off >>= 1) {
            const int o = __shfl_xor_sync(0xffffffffu, te_l, off);
            te_l = (o < te_l) ? o : te_l;
        }
        if (lane == 0) s_te[wid] = te_l;
        __syncthreads();
        const int te = (s_te[slot * 2] < s_te[slot * 2 + 1]) ? s_te[slot * 2] : s_te[slot * 2 + 1];

        float vte = 0.f;
        switch (te) {                              // uniform
            case 0:  vte = acc[0];  break;  case 1:  vte = acc[1];  break;
            case 2:  vte = acc[2];  break;  case 3:  vte = acc[3];  break;
            case 4:  vte = acc[4];  break;  case 5:  vte = acc[5];  break;
            case 6:  vte = acc[6];  break;  case 7:  vte = acc[7];  break;
            case 8:  vte = acc[8];  break;  case 9:  vte = acc[9];  break;
            case 10: vte = acc[10]; break;  case 11: vte = acc[11]; break;
            case 12: vte = acc[12]; break;  case 13: vte = acc[13]; break;
            case 14: vte = acc[14]; break;  default: break;
        }
        vte = (vte >= THRESH) ? vte : 0.f;

        unsigned long long key =
            ((unsigned long long)__float_as_uint(vte) << 32) | (unsigned)(255 - ch);
#pragma unroll
        for (int off = 16; off; off >>= 1) {
            const unsigned long long o = __shfl_xor_sync(0xffffffffu, key, off);
            if (o > key) key = o;
        }
        if (lane == 0) s_key[wid] = key;
        __syncthreads();
        {
            const unsigned long long k0 = s_key[slot * 2], k1 = s_key[slot * 2 + 1];
            const unsigned long long kk = (k0 > k1) ? k0 : k1;
            const int cw = 255 - (int)(kk & 0xffull);
            if (te < 15) {
                if (ch == cw) {
                    g_winfo[pix]    = cw | ((15 - te) << 8);
                    g_wc[pix]       = (unsigned char)cw;
                    g_firstpot[pix] = __uint_as_float((unsigned)(kk >> 32));
                    atomicMax(&g_vmax, (int)(kk >> 32));
#pragma unroll
                    for (int t = 0; t < 15; t++)
                        g_winval[(size_t)pix * 16 + t] = (acc[t] >= THRESH) ? acc[t] : 0.f;
                }
            } else if (half == 0 && lane == 0) {
                g_winfo[pix]    = -1;
                g_wc[pix]       = 255;
                g_firstpot[pix] = 0.f;
            }
        }
        __syncthreads();
    }
}

// ---------------------------------------------------------------------------
// K2: emit spk/pot: zeros everywhere except winner channel, which takes the
// stored thresholded values. Pure streaming float4 stores.
// ---------------------------------------------------------------------------
__global__ __launch_bounds__(256) void emit_kernel(float* __restrict__ spk,
                                                   float* __restrict__ pot)
{
    const size_t u = (size_t)blockIdx.x * 256 + threadIdx.x;  // NELEM/4 units
    const int w4 = (int)(u & 63);
    size_t rr = u >> 6;
    const int h = (int)(rr & 255); rr >>= 8;
    const int c = (int)(rr & 63);
    const int t = (int)(rr >> 6);

    const int pix = (h << 8) | (w4 << 2);
    const uchar4 wc = *reinterpret_cast<const uchar4*>(g_wc + pix);
    const size_t e = ((size_t)t * C_OUT + (size_t)c) * NPIX + (size_t)pix;

    float4 pv, sv;
    float v;
    v = (wc.x == c) ? g_winval[(size_t)(pix + 0) * 16 + t] : 0.f; pv.x = v; sv.x = (v > 0.f) ? 1.f : 0.f;
    v = (wc.y == c) ? g_winval[(size_t)(pix + 1) * 16 + t] : 0.f; pv.y = v; sv.y = (v > 0.f) ? 1.f : 0.f;
    v = (wc.z == c) ? g_winval[(size_t)(pix + 2) * 16 + t] : 0.f; pv.z = v; sv.z = (v > 0.f) ? 1.f : 0.f;
    v = (wc.w == c) ? g_winval[(size_t)(pix + 3) * 16 + t] : 0.f; pv.w = v; sv.w = (v > 0.f) ? 1.f : 0.f;

    *reinterpret_cast<float4*>(pot + e) = pv;
    *reinterpret_cast<float4*>(spk + e) = sv;
}

// ---------------------------------------------------------------------------
// K3a/K3b: parallel k-WTA. Per round: 64-block partial argmax over pixels
// (respecting accumulated channel + 7x7 box bans), then a 32-thread final
// reduce that appends the ban and writes the output row.
// key = tot-bits<<32 | ~flat  (max tot, ties -> lowest flat (c,h,w) index).
// ---------------------------------------------------------------------------
__global__ __launch_bounds__(256) void kwta_partial(int round)
{
    __shared__ unsigned long long sk[256];
    const int tid = threadIdx.x;
    const float v = __int_as_float(g_vmax) * (float)T_STEPS;

    int bc[4], bh[4], bw[4];
#pragma unroll
    for (int b = 0; b < 4; b++) {
        if (b < round) { bc[b] = g_banc[b]; const int bp = g_banp[b]; bh[b] = bp >> 8; bw[b] = bp & 255; }
        else           { bc[b] = -1; bh[b] = -1000; bw[b] = -1000; }
    }

    unsigned long long best = 0;
    for (int p = blockIdx.x * 256 + tid; p < NPIX; p += 64 * 256) {
        const int info = g_winfo[p];
        if (info < 0) continue;
        const int wc = info & 255;
        const int h = p >> 8, w = p & 255;
        bool ban = false;
#pragma unroll
        for (int b = 0; b < 4; b++) {
            if (wc == bc[b]) ban = true;
            if (h >= bh[b] - 3 && h <= bh[b] + 3 && w >= bw[b] - 3 && w <= bw[b] + 3) ban = true;
        }
        if (ban) continue;
        const float tot = (float)(info >> 8) * (g_firstpot[p] + v);
        const unsigned flat = ((unsigned)wc << 16) | (unsigned)p;
        const unsigned long long key =
            ((unsigned long long)__float_as_uint(tot) << 32) | (unsigned)(~flat);
        if (key > best) best = key;
    }
    sk[tid] = best;
    __syncthreads();
    for (int s = 128; s >= 1; s >>= 1) {
        if (tid < s) { if (sk[tid + s] > sk[tid]) sk[tid] = sk[tid + s]; }
        __syncthreads();
    }
    if (tid == 0) g_part[blockIdx.x] = sk[0];
}

__global__ __launch_bounds__(32) void kwta_final(int round, float* __restrict__ owin)
{
    const int tid = threadIdx.x;
    unsigned long long k = g_part[tid];
    const unsigned long long k2 = g_part[tid + 32];
    if (k2 > k) k = k2;
#pragma unroll
    for (int off = 16; off; off >>= 1) {
        const unsigned long long o = __shfl_xor_sync(0xffffffffu, k, off);
        if (o > k) k = o;
    }
    if (tid == 0) {
        if ((k >> 32) != 0ull) {
            const unsigned flat = ~(unsigned)(k & 0xffffffffull);
            const int c = (int)(flat >> 16), p = (int)(flat & 0xffff);
            const int h = p >> 8, w = p & 255;
            owin[round * 3 + 0] = (float)c;
            owin[round * 3 + 1] = (float)h;
            owin[round * 3 + 2] = (float)w;
            g_banc[round] = c;
            g_banp[round] = (h << 8) | w;
        } else {
            owin[round * 3 + 0] = -1.f;
            owin[round * 3 + 1] = -1.f;
            owin[round * 3 + 2] = -1.f;
            g_banc[round] = -1;
            g_banp[round] = (1000 << 8);
        }
    }
}

// ---------------------------------------------------------------------------
extern "C" void kernel_launch(void* const* d_in, const int* in_sizes, int n_in,
                              void* d_out, int out_size)
{
    (void)in_sizes; (void)n_in; (void)out_size;
    const float* in = (const float*)d_in[0];
    const float* w1 = (const float*)d_in[1];

    float* out = (float*)d_out;
    float* spk = out;
    float* pot = out + (size_t)NELEM;
    float* win = out + (size_t)2 * NELEM;

    ft_kernel<<<(C_IN * NPIX) / 256, 256>>>(in);
    ftq_kernel<<<dim3(16, 16), 256>>>();
    conv_kernel<<<NPIX / 64, 256>>>(w1);
    emit_kernel<<<NELEM / 4 / 256, 256>>>(spk, pot);
    for (int r = 0; r < 5; r++) {
        kwta_partial<<<64, 256>>>(r);
        kwta_final<<<1, 32>>>(r, win);
    }
}

// round 4
// speedup vs baseline: 2.3498x; 2.3498x over previous
#include <cuda_runtime.h>
#include <stdint.h>

#define T_STEPS 15
#define C_IN    6
#define HW      256
#define NPIX    65536
#define C_OUT   64
#define THRESH  15.0f
#define NELEM   62914560         // 15*64*256*256
#define NTAP    150

// small per-pixel maps (device globals; no allocation)
__device__ float               g_max [T_STEPS * NPIX];
__device__ unsigned char       g_amax[T_STEPS * NPIX];
__device__ int                 g_winfo[NPIX];            // -1 or wc | (count<<8)
__device__ float               g_firstpot[NPIX];
__device__ int                 g_vmax = 0;               // float bits of max firstpot (idempotent atomicMax)
__device__ unsigned long long  g_part[64];
__device__ int                 g_banc[5];
__device__ int                 g_banp[5];

// ---------------------------------------------------------------------------
// K1: 5x5 conv (6->64), one t per block-z, 32x8 pixel tile, fused threshold,
// stages thr_pot into the `pot` output region, reduces per-pixel max/argmax.
// Math: ONE sequential fp32 chain per output in (ky,kx,i) order — but executed
// as packed fma.rn.f32x2 over channel pairs (element-wise identical rounding).
// ---------------------------------------------------------------------------
__global__ __launch_bounds__(256) void conv_kernel(const float* __restrict__ in,
                                                   const float* __restrict__ wg,
                                                   float* __restrict__ pot)
{
    __shared__ __align__(16) float ws[NTAP * 64];   // [q][c]  38400 B
    __shared__ float xs[C_IN * 12 * 36];            // 10368 B (total 48768 < 49152)

    const int t   = blockIdx.z;
    const int x0  = blockIdx.x * 32;
    const int y0  = blockIdx.y * 8;
    const int tid = threadIdx.x;

    // OIHW -> ws[q*64 + c], q = (ky*5+kx)*6 + i
    for (int k = tid; k < C_OUT * NTAP; k += 256) {
        const int c = k / NTAP, rr = k % NTAP;
        const int i = rr / 25, r2 = rr % 25, ky = r2 / 5, kx = r2 % 5;
        ws[((ky * 5 + kx) * 6 + i) * 64 + c] = wg[k];
    }

    const float* inT = in + (size_t)t * C_IN * NPIX;
    for (int k = tid; k < C_IN * 12 * 36; k += 256) {
        int i  = k / (12 * 36);
        int r  = k % (12 * 36);
        int hy = r / 36, hx = r % 36;
        int gy = y0 + hy - 2, gx = x0 + hx - 2;
        float v = 0.f;
        if (gy >= 0 && gy < HW && gx >= 0 && gx < HW)
            v = inT[i * NPIX + gy * HW + gx];
        xs[k] = v;
    }
    __syncthreads();

    const int lw = tid & 31;
    const int cg = tid >> 5;

    // acc2[h][m] holds channel pair (cg*8+2m, cg*8+2m+1), packed f32x2
    unsigned long long acc2[8][4];
#pragma unroll
    for (int h = 0; h < 8; h++)
#pragma unroll
        for (int m = 0; m < 4; m++) acc2[h][m] = 0ull;

    for (int ky = 0; ky < 5; ky++) {
#pragma unroll
        for (int kx = 0; kx < 5; kx++) {
#pragma unroll
            for (int i = 0; i < C_IN; i++) {
                const int q = (ky * 5 + kx) * 6 + i;
                unsigned long long wv2[4];
#pragma unroll
                for (int m = 0; m < 4; m++)
                    wv2[m] = *reinterpret_cast<const unsigned long long*>(
                                 &ws[q * 64 + cg * 8 + 2 * m]);
                unsigned long long xx[8];
#pragma unroll
                for (int h = 0; h < 8; h++) {
                    const float xv = xs[(i * 12 + ky + h) * 36 + lw + kx];
                    asm("mov.b64 %0, {%1, %1};" : "=l"(xx[h]) : "f"(xv));
                }
#pragma unroll
                for (int h = 0; h < 8; h++)
#pragma unroll
                    for (int m = 0; m < 4; m++)
                        asm("fma.rn.f32x2 %0, %1, %2, %0;"
                            : "+l"(acc2[h][m]) : "l"(xx[h]), "l"(wv2[m]));
            }
        }
    }

    // unpack
    float acc[8][8];
#pragma unroll
    for (int h = 0; h < 8; h++)
#pragma unroll
        for (int m = 0; m < 4; m++)
            asm("mov.b64 {%0, %1}, %2;"
                : "=f"(acc[h][2 * m]), "=f"(acc[h][2 * m + 1]) : "l"(acc2[h][m]));

    __syncthreads();   // done with ws/xs; reuse ws as reduction scratch

    float* redv = ws;                    // [cg*8+h][lw]
    int*   redi = (int*)(ws + 2048);

#pragma unroll
    for (int h = 0; h < 8; h++) {
        float bv = -1.f;
        int   bc = 0;
        const size_t rowbase = (((size_t)t * C_OUT) * HW + (size_t)(y0 + h)) * HW + x0 + lw;
#pragma unroll
        for (int j = 0; j < 8; j++) {
            const int c = cg * 8 + j;
            float v = acc[h][j];
            v = (v >= THRESH) ? v : 0.f;
            pot[rowbase + (size_t)c * NPIX] = v;
            if (v > bv) { bv = v; bc = c; }
        }
        redv[(cg * 8 + h) * 32 + lw] = bv;
        redi[(cg * 8 + h) * 32 + lw] = bc;
    }
    __syncthreads();

    for (int s = 4; s >= 1; s >>= 1) {
        if (cg < s) {
#pragma unroll
            for (int h = 0; h < 8; h++) {
                const int a = (cg * 8 + h) * 32 + lw;
                const int b = ((cg + s) * 8 + h) * 32 + lw;
                const float vL = redv[a], vR = redv[b];
                if (vR > vL) { redv[a] = vR; redi[a] = redi[b]; }
            }
        }
        __syncthreads();
    }

    if (cg == 0) {
#pragma unroll
        for (int h = 0; h < 8; h++) {
            const int pix = (y0 + h) * HW + x0 + lw;
            g_max [t * NPIX + pix] = redv[h * 32 + lw];
            g_amax[t * NPIX + pix] = (unsigned char)redi[h * 32 + lw];
        }
    }
}

// ---------------------------------------------------------------------------
// K2: per pixel earliest firing time -> winfo/firstpot; fold vmax (idempotent).
// ---------------------------------------------------------------------------
__global__ void winner_kernel()
{
    const int p = blockIdx.x * blockDim.x + threadIdx.x;
    if (p >= NPIX) return;
    int   info = -1;
    float fp   = 0.f;
    for (int t = 0; t < T_STEPS; t++) {
        const float m = g_max[t * NPIX + p];
        if (m > 0.f) {
            info = (int)g_amax[t * NPIX + p] | ((T_STEPS - t) << 8);
            fp   = m;
            break;
        }
    }
    g_winfo[p]    = info;
    g_firstpot[p] = fp;
    if (fp > 0.f) atomicMax(&g_vmax, __float_as_int(fp));
}

// ---------------------------------------------------------------------------
// K3: pointwise-inhibition materialization (in-place rewrite of pot) + spk.
// ---------------------------------------------------------------------------
__global__ __launch_bounds__(256) void emit_kernel(float* __restrict__ spk,
                                                   float* __restrict__ pot)
{
    const size_t u = (size_t)blockIdx.x * 256 + threadIdx.x; // NELEM/4 units
    const int w4 = (int)(u & 63);
    size_t r = u >> 6;
    const int h = (int)(r & 255); r >>= 8;
    const int c = (int)(r & 63);
    const int t = (int)(r >> 6);

    const int pix = (h << 8) | (w4 << 2);
    const int4 wi = *reinterpret_cast<const int4*>(g_winfo + pix);
    const size_t e = ((size_t)t * C_OUT + (size_t)c) * NPIX + (size_t)pix;

    float4 pv, sv;
    float v;
    v = (wi.x >= 0 && (wi.x & 255) == c) ? pot[e + 0] : 0.f; pv.x = v; sv.x = (v > 0.f) ? 1.f : 0.f;
    v = (wi.y >= 0 && (wi.y & 255) == c) ? pot[e + 1] : 0.f; pv.y = v; sv.y = (v > 0.f) ? 1.f : 0.f;
    v = (wi.z >= 0 && (wi.z & 255) == c) ? pot[e + 2] : 0.f; pv.z = v; sv.z = (v > 0.f) ? 1.f : 0.f;
    v = (wi.w >= 0 && (wi.w & 255) == c) ? pot[e + 3] : 0.f; pv.w = v; sv.w = (v > 0.f) ? 1.f : 0.f;

    *reinterpret_cast<float4*>(pot + e) = pv;
    *reinterpret_cast<float4*>(spk + e) = sv;
}

// ---------------------------------------------------------------------------
// K4a/K4b: parallel k-WTA, 5 greedy rounds.
// key = tot-bits<<32 | ~flat  (max tot, ties -> lowest flat (c,h,w)).
// ---------------------------------------------------------------------------
__global__ __launch_bounds__(256) void kwta_partial(int round)
{
    __shared__ unsigned long long sk[256];
    const int tid = threadIdx.x;
    const float v = __int_as_float(g_vmax) * (float)T_STEPS;

    int bc[4], bh[4], bw[4];
#pragma unroll
    for (int b = 0; b < 4; b++) {
        if (b < round) { bc[b] = g_banc[b]; const int bp = g_banp[b]; bh[b] = bp >> 8; bw[b] = bp & 255; }
        else           { bc[b] = -1; bh[b] = -1000; bw[b] = -1000; }
    }

    unsigned long long best = 0;
    for (int p = blockIdx.x * 256 + tid; p < NPIX; p += 64 * 256) {
        const int info = g_winfo[p];
        if (info < 0) continue;
        const int wc = info & 255;
        const int h = p >> 8, w = p & 255;
        bool ban = false;
#pragma unroll
        for (int b = 0; b < 4; b++) {
            if (wc == bc[b]) ban = true;
            if (h >= bh[b] - 3 && h <= bh[b] + 3 && w >= bw[b] - 3 && w <= bw[b] + 3) ban = true;
        }
        if (ban) continue;
        const float tot = (float)(info >> 8) * (g_firstpot[p] + v);
        const unsigned flat = ((unsigned)wc << 16) | (unsigned)p;
        const unsigned long long key =
            ((unsigned long long)__float_as_uint(tot) << 32) | (unsigned)(~flat);
        if (key > best) best = key;
    }
    sk[tid] = best;
    __syncthreads();
    for (int s = 128; s >= 1; s >>= 1) {
        if (tid < s) { if (sk[tid + s] > sk[tid]) sk[tid] = sk[tid + s]; }
        __syncthreads();
    }
    if (tid == 0) g_part[blockIdx.x] = sk[0];
}

__global__ __launch_bounds__(32) void kwta_final(int round, float* __restrict__ owin)
{
    const int tid = threadIdx.x;
    unsigned long long k = g_part[tid];
    const unsigned long long k2 = g_part[tid + 32];
    if (k2 > k) k = k2;
#pragma unroll
    for (int off = 16; off; off >>= 1) {
        const unsigned long long o = __shfl_xor_sync(0xffffffffu, k, off);
        if (o > k) k = o;
    }
    if (tid == 0) {
        if ((k >> 32) != 0ull) {
            const unsigned flat = ~(unsigned)(k & 0xffffffffull);
            const int c = (int)(flat >> 16), p = (int)(flat & 0xffff);
            const int h = p >> 8, w = p & 255;
            owin[round * 3 + 0] = (float)c;
            owin[round * 3 + 1] = (float)h;
            owin[round * 3 + 2] = (float)w;
            g_banc[round] = c;
            g_banp[round] = (h << 8) | w;
        } else {
            owin[round * 3 + 0] = -1.f;
            owin[round * 3 + 1] = -1.f;
            owin[round * 3 + 2] = -1.f;
            g_banc[round] = -1;
            g_banp[round] = (1000 << 8);
        }
    }
}

// ---------------------------------------------------------------------------
extern "C" void kernel_launch(void* const* d_in, const int* in_sizes, int n_in,
                              void* d_out, int out_size)
{
    (void)in_sizes; (void)n_in; (void)out_size;
    const float* in = (const float*)d_in[0];
    const float* w1 = (const float*)d_in[1];

    float* out = (float*)d_out;
    float* spk = out;
    float* pot = out + (size_t)NELEM;
    float* win = out + (size_t)2 * NELEM;

    conv_kernel<<<dim3(8, 32, 15), 256>>>(in, w1, pot);
    winner_kernel<<<NPIX / 256, 256>>>();
    emit_kernel<<<NELEM / 4 / 256, 256>>>(spk, pot);
    for (int r = 0; r < 5; r++) {
        kwta_partial<<<64, 256>>>(r);
        kwta_final<<<1, 32>>>(r, win);
    }
}

// round 5
// speedup vs baseline: 2.3538x; 1.0017x over previous
#include <cuda_runtime.h>
#include <stdint.h>

#define T_STEPS 15
#define C_IN    6
#define HW      256
#define NPIX    65536
#define C_OUT   64
#define THRESH  15.0f
#define NELEM   62914560         // 15*64*256*256
#define NTAP    150

// small per-pixel maps (device globals; no allocation)
__device__ float               g_max [T_STEPS * NPIX];
__device__ unsigned char       g_amax[T_STEPS * NPIX];
__device__ int                 g_winfo[NPIX];            // -1 or wc | (count<<8)
__device__ float               g_firstpot[NPIX];
__device__ int                 g_vmax = 0;               // float bits of max firstpot (idempotent atomicMax)
__device__ unsigned long long  g_part[64];
__device__ int                 g_banc[5];
__device__ int                 g_banp[5];

// ---------------------------------------------------------------------------
// K1: 5x5 conv (6->64), one t per block-z, 32x8 pixel tile, fused threshold,
// stages thr_pot into the `pot` output region, reduces per-pixel max/argmax.
// Math: ONE sequential fp32 chain per output in (ky,kx,i) order — but executed
// as packed fma.rn.f32x2 over channel pairs (element-wise identical rounding).
// ---------------------------------------------------------------------------
__global__ __launch_bounds__(256) void conv_kernel(const float* __restrict__ in,
                                                   const float* __restrict__ wg,
                                                   float* __restrict__ pot)
{
    __shared__ __align__(16) float ws[NTAP * 64];   // [q][c]  38400 B
    __shared__ float xs[C_IN * 12 * 36];            // 10368 B (total 48768 < 49152)

    const int t   = blockIdx.z;
    const int x0  = blockIdx.x * 32;
    const int y0  = blockIdx.y * 8;
    const int tid = threadIdx.x;

    // OIHW -> ws[q*64 + c], q = (ky*5+kx)*6 + i
    for (int k = tid; k < C_OUT * NTAP; k += 256) {
        const int c = k / NTAP, rr = k % NTAP;
        const int i = rr / 25, r2 = rr % 25, ky = r2 / 5, kx = r2 % 5;
        ws[((ky * 5 + kx) * 6 + i) * 64 + c] = wg[k];
    }

    const float* inT = in + (size_t)t * C_IN * NPIX;
    for (int k = tid; k < C_IN * 12 * 36; k += 256) {
        int i  = k / (12 * 36);
        int r  = k % (12 * 36);
        int hy = r / 36, hx = r % 36;
        int gy = y0 + hy - 2, gx = x0 + hx - 2;
        float v = 0.f;
        if (gy >= 0 && gy < HW && gx >= 0 && gx < HW)
            v = inT[i * NPIX + gy * HW + gx];
        xs[k] = v;
    }
    __syncthreads();

    const int lw = tid & 31;
    const int cg = tid >> 5;

    // acc2[h][m] holds channel pair (cg*8+2m, cg*8+2m+1), packed f32x2
    unsigned long long acc2[8][4];
#pragma unroll
    for (int h = 0; h < 8; h++)
#pragma unroll
        for (int m = 0; m < 4; m++) acc2[h][m] = 0ull;

    for (int ky = 0; ky < 5; ky++) {
#pragma unroll
        for (int kx = 0; kx < 5; kx++) {
#pragma unroll
            for (int i = 0; i < C_IN; i++) {
                const int q = (ky * 5 + kx) * 6 + i;
                unsigned long long wv2[4];
#pragma unroll
                for (int m = 0; m < 4; m++)
                    wv2[m] = *reinterpret_cast<const unsigned long long*>(
                                 &ws[q * 64 + cg * 8 + 2 * m]);
                unsigned long long xx[8];
#pragma unroll
                for (int h = 0; h < 8; h++) {
                    const float xv = xs[(i * 12 + ky + h) * 36 + lw + kx];
                    asm("mov.b64 %0, {%1, %1};" : "=l"(xx[h]) : "f"(xv));
                }
#pragma unroll
                for (int h = 0; h < 8; h++)
#pragma unroll
                    for (int m = 0; m < 4; m++)
                        asm("fma.rn.f32x2 %0, %1, %2, %0;"
                            : "+l"(acc2[h][m]) : "l"(xx[h]), "l"(wv2[m]));
            }
        }
    }

    // unpack
    float acc[8][8];
#pragma unroll
    for (int h = 0; h < 8; h++)
#pragma unroll
        for (int m = 0; m < 4; m++)
            asm("mov.b64 {%0, %1}, %2;"
                : "=f"(acc[h][2 * m]), "=f"(acc[h][2 * m + 1]) : "l"(acc2[h][m]));

    __syncthreads();   // done with ws/xs; reuse ws as reduction scratch

    float* redv = ws;                    // [cg*8+h][lw]
    int*   redi = (int*)(ws + 2048);

#pragma unroll
    for (int h = 0; h < 8; h++) {
        float bv = -1.f;
        int   bc = 0;
        const size_t rowbase = (((size_t)t * C_OUT) * HW + (size_t)(y0 + h)) * HW + x0 + lw;
#pragma unroll
        for (int j = 0; j < 8; j++) {
            const int c = cg * 8 + j;
            float v = acc[h][j];
            v = (v >= THRESH) ? v : 0.f;
            pot[rowbase + (size_t)c * NPIX] = v;
            if (v > bv) { bv = v; bc = c; }
        }
        redv[(cg * 8 + h) * 32 + lw] = bv;
        redi[(cg * 8 + h) * 32 + lw] = bc;
    }
    __syncthreads();

    for (int s = 4; s >= 1; s >>= 1) {
        if (cg < s) {
#pragma unroll
            for (int h = 0; h < 8; h++) {
                const int a = (cg * 8 + h) * 32 + lw;
                const int b = ((cg + s) * 8 + h) * 32 + lw;
                const float vL = redv[a], vR = redv[b];
                if (vR > vL) { redv[a] = vR; redi[a] = redi[b]; }
            }
        }
        __syncthreads();
    }

    if (cg == 0) {
#pragma unroll
        for (int h = 0; h < 8; h++) {
            const int pix = (y0 + h) * HW + x0 + lw;
            g_max [t * NPIX + pix] = redv[h * 32 + lw];
            g_amax[t * NPIX + pix] = (unsigned char)redi[h * 32 + lw];
        }
    }
}

// ---------------------------------------------------------------------------
// K2: per pixel earliest firing time -> winfo/firstpot; fold vmax (idempotent).
// ---------------------------------------------------------------------------
__global__ void winner_kernel()
{
    const int p = blockIdx.x * blockDim.x + threadIdx.x;
    if (p >= NPIX) return;
    int   info = -1;
    float fp   = 0.f;
    for (int t = 0; t < T_STEPS; t++) {
        const float m = g_max[t * NPIX + p];
        if (m > 0.f) {
            info = (int)g_amax[t * NPIX + p] | ((T_STEPS - t) << 8);
            fp   = m;
            break;
        }
    }
    g_winfo[p]    = info;
    g_firstpot[p] = fp;
    if (fp > 0.f) atomicMax(&g_vmax, __float_as_int(fp));
}

// ---------------------------------------------------------------------------
// K3: pointwise-inhibition materialization (in-place rewrite of pot) + spk.
// ---------------------------------------------------------------------------
__global__ __launch_bounds__(256) void emit_kernel(float* __restrict__ spk,
                                                   float* __restrict__ pot)
{
    const size_t u = (size_t)blockIdx.x * 256 + threadIdx.x; // NELEM/4 units
    const int w4 = (int)(u & 63);
    size_t r = u >> 6;
    const int h = (int)(r & 255); r >>= 8;
    const int c = (int)(r & 63);
    const int t = (int)(r >> 6);

    const int pix = (h << 8) | (w4 << 2);
    const int4 wi = *reinterpret_cast<const int4*>(g_winfo + pix);
    const size_t e = ((size_t)t * C_OUT + (size_t)c) * NPIX + (size_t)pix;

    float4 pv, sv;
    float v;
    v = (wi.x >= 0 && (wi.x & 255) == c) ? pot[e + 0] : 0.f; pv.x = v; sv.x = (v > 0.f) ? 1.f : 0.f;
    v = (wi.y >= 0 && (wi.y & 255) == c) ? pot[e + 1] : 0.f; pv.y = v; sv.y = (v > 0.f) ? 1.f : 0.f;
    v = (wi.z >= 0 && (wi.z & 255) == c) ? pot[e + 2] : 0.f; pv.z = v; sv.z = (v > 0.f) ? 1.f : 0.f;
    v = (wi.w >= 0 && (wi.w & 255) == c) ? pot[e + 3] : 0.f; pv.w = v; sv.w = (v > 0.f) ? 1.f : 0.f;

    *reinterpret_cast<float4*>(pot + e) = pv;
    *reinterpret_cast<float4*>(spk + e) = sv;
}

// ---------------------------------------------------------------------------
// K4a/K4b: parallel k-WTA, 5 greedy rounds.
// key = tot-bits<<32 | ~flat  (max tot, ties -> lowest flat (c,h,w)).
// ---------------------------------------------------------------------------
__global__ __launch_bounds__(256) void kwta_partial(int round)
{
    __shared__ unsigned long long sk[256];
    const int tid = threadIdx.x;
    const float v = __int_as_float(g_vmax) * (float)T_STEPS;

    int bc[4], bh[4], bw[4];
#pragma unroll
    for (int b = 0; b < 4; b++) {
        if (b < round) { bc[b] = g_banc[b]; const int bp = g_banp[b]; bh[b] = bp >> 8; bw[b] = bp & 255; }
        else           { bc[b] = -1; bh[b] = -1000; bw[b] = -1000; }
    }

    unsigned long long best = 0;
    for (int p = blockIdx.x * 256 + tid; p < NPIX; p += 64 * 256) {
        const int info = g_winfo[p];
        if (info < 0) continue;
        const int wc = info & 255;
        const int h = p >> 8, w = p & 255;
        bool ban = false;
#pragma unroll
        for (int b = 0; b < 4; b++) {
            if (wc == bc[b]) ban = true;
            if (h >= bh[b] - 3 && h <= bh[b] + 3 && w >= bw[b] - 3 && w <= bw[b] + 3) ban = true;
        }
        if (ban) continue;
        const float tot = (float)(info >> 8) * (g_firstpot[p] + v);
        const unsigned flat = ((unsigned)wc << 16) | (unsigned)p;
        const unsigned long long key =
            ((unsigned long long)__float_as_uint(tot) << 32) | (unsigned)(~flat);
        if (key > best) best = key;
    }
    sk[tid] = best;
    __syncthreads();
    for (int s = 128; s >= 1; s >>= 1) {
        if (tid < s) { if (sk[tid + s] > sk[tid]) sk[tid] = sk[tid + s]; }
        __syncthreads();
    }
    if (tid == 0) g_part[blockIdx.x] = sk[0];
}

__global__ __launch_bounds__(32) void kwta_final(int round, float* __restrict__ owin)
{
    const int tid = threadIdx.x;
    unsigned long long k = g_part[tid];
    const unsigned long long k2 = g_part[tid + 32];
    if (k2 > k) k = k2;
#pragma unroll
    for (int off = 16; off; off >>= 1) {
        const unsigned long long o = __shfl_xor_sync(0xffffffffu, k, off);
        if (o > k) k = o;
    }
    if (tid == 0) {
        if ((k >> 32) != 0ull) {
            const unsigned flat = ~(unsigned)(k & 0xffffffffull);
            const int c = (int)(flat >> 16), p = (int)(flat & 0xffff);
            const int h = p >> 8, w = p & 255;
            owin[round * 3 + 0] = (float)c;
            owin[round * 3 + 1] = (float)h;
            owin[round * 3 + 2] = (float)w;
            g_banc[round] = c;
            g_banp[round] = (h << 8) | w;
        } else {
            owin[round * 3 + 0] = -1.f;
            owin[round * 3 + 1] = -1.f;
            owin[round * 3 + 2] = -1.f;
            g_banc[round] = -1;
            g_banp[round] = (1000 << 8);
        }
    }
}

// ---------------------------------------------------------------------------
extern "C" void kernel_launch(void* const* d_in, const int* in_sizes, int n_in,
                              void* d_out, int out_size)
{
    (void)in_sizes; (void)n_in; (void)out_size;
    const float* in = (const float*)d_in[0];
    const float* w1 = (const float*)d_in[1];

    float* out = (float*)d_out;
    float* spk = out;
    float* pot = out + (size_t)NELEM;
    float* win = out + (size_t)2 * NELEM;

    conv_kernel<<<dim3(8, 32, 15), 256>>>(in, w1, pot);
    winner_kernel<<<NPIX / 256, 256>>>();
    emit_kernel<<<NELEM / 4 / 256, 256>>>(spk, pot);
    for (int r = 0; r < 5; r++) {
        kwta_partial<<<64, 256>>>(r);
        kwta_final<<<1, 32>>>(r, win);
    }
}